// round 16
// baseline (speedup 1.0000x reference)
#include <cuda_runtime.h>
#include <cuda_fp16.h>
#include <cstdint>

// BahdanauScorer: scores[b,s] = sum_a v_a[a] * tanh( enc[s,b,:].W_s[a,:] + dec[b,:].W_t[a,:] + b_t[a] )
// enc (2048,64,512) f32; dec (64,512); W_s,W_t (512,512); b_t,v_a (512); out (64,2048) f32.
//
// fp16 mma.sync, BARRIER-FREE main loop:
//  - A (enc slab 64x512 fp16) persistent in smem, converted once in prologue (1 barrier).
//  - B fragments loaded DIRECTLY from gmem W (L2-resident) via LDG.32 with immediate
//    offsets -- the m16n8k16 col-B fragment layout coincides with row-major W.
//  - No cp.async, no B smem, no per-iteration __syncthreads; warps fully async.

#define S_LEN  2048
#define BATCH  64
#define HID    512
#define ATT    512
#define MT     64       // s-rows per CTA
#define AC_N   128      // a per chunk
#define KC     64       // k per chunk (floats)
#define NTHR   256

// device scratch
__device__ float  g_dec_att[BATCH * ATT];
__device__ __half g_W_h[ATT * HID];

// smem: A 64KB (8 tiles x 8KB, one per kc) + dec/v/score
#define OFF_A    0
#define SM_DEC   65536
#define SM_V     67584
#define SM_SCORE 69632
#define SM_TOTAL 69888

__device__ __forceinline__ uint32_t smem_u32(const void* p) {
    uint32_t a;
    asm("{ .reg .u64 t; cvta.to.shared.u64 t, %1; cvt.u32.u64 %0, t; }" : "=r"(a) : "l"(p));
    return a;
}
__device__ __forceinline__ void ldsm4(uint32_t addr, uint32_t* r) {
    asm volatile("ldmatrix.sync.aligned.m8n8.x4.shared.b16 {%0,%1,%2,%3}, [%4];"
                 : "=r"(r[0]), "=r"(r[1]), "=r"(r[2]), "=r"(r[3]) : "r"(addr));
}

#define MMA(d, a, b0, b1)                                                        \
    asm volatile("mma.sync.aligned.m16n8k16.row.col.f32.f16.f16.f32 "            \
                 "{%0,%1,%2,%3},{%4,%5,%6,%7},{%8,%9},{%0,%1,%2,%3};"            \
                 : "+f"((d)[0]), "+f"((d)[1]), "+f"((d)[2]), "+f"((d)[3])        \
                 : "r"((a)[0]), "r"((a)[1]), "r"((a)[2]), "r"((a)[3]),           \
                   "r"(b0), "r"(b1))

__device__ __forceinline__ float tanh_fast(float x) {
    float y;
    asm("tanh.approx.f32 %0, %1;" : "=f"(y) : "f"(x));
    return y;
}
__device__ __forceinline__ uint32_t cvt2h(float x0, float x1) {
    __half2 h = __floats2half2_rn(x0, x1);
    return *reinterpret_cast<uint32_t*>(&h);
}

// ---------------- merged prep kernel ----------------
// blocks 0..511: W_s -> fp16.  blocks 512..767: dec_att (4 blocks per batch).
__global__ void prep_kernel(const float* __restrict__ W_s,
                            const float* __restrict__ dec_out,
                            const float* __restrict__ W_t,
                            const float* __restrict__ b_t) {
    if (blockIdx.x < 512) {
        int i = blockIdx.x * 512 + threadIdx.x;
        g_W_h[i] = __float2half_rn(W_s[i]);
    } else {
        const int bq = blockIdx.x - 512;
        const int b = bq >> 2, aq = bq & 3;
        __shared__ float dsh[HID];
        for (int i = threadIdx.x; i < HID; i += blockDim.x)
            dsh[i] = dec_out[b * HID + i];
        __syncthreads();
        const int a = aq * 128 + (threadIdx.x >> 2);
        const int part = threadIdx.x & 3;
        const float4* w4 = reinterpret_cast<const float4*>(W_t + (size_t)a * HID) + part * 32;
        const float4* d4 = reinterpret_cast<const float4*>(dsh) + part * 32;
        float acc = 0.f;
#pragma unroll 8
        for (int h4 = 0; h4 < 32; ++h4) {
            float4 w = __ldg(&w4[h4]);
            float4 d = d4[h4];
            acc += w.x * d.x + w.y * d.y + w.z * d.z + w.w * d.w;
        }
        acc += __shfl_down_sync(0xffffffffu, acc, 1);
        acc += __shfl_down_sync(0xffffffffu, acc, 2);
        if (part == 0) g_dec_att[b * ATT + a] = acc + b_t[a];
    }
}

// ---------------- main kernel ----------------
extern "C" __global__ void __launch_bounds__(NTHR, 2)
score_mma_kernel(const float* __restrict__ enc,
                 const float* __restrict__ v_a,
                 float* __restrict__ out) {
    extern __shared__ char smem[];
    const uint32_t sb = smem_u32(smem);
    const int tid = threadIdx.x;
    const int lane = tid & 31, wid = tid >> 5;
    const int g = lane >> 2, c = lane & 3, l7 = lane & 7;
    const int t8 = (lane >> 3) & 1, t16 = lane >> 4;
    const int wm = wid & 1, wn = wid >> 1;     // 2 x 4 warp grid
    const int mbase = wm * 32, nbase = wn * 32;
    const int b = blockIdx.y, s0 = blockIdx.x * MT;

    float* dec_s = reinterpret_cast<float*>(smem + SM_DEC);
    float* v_s   = reinterpret_cast<float*>(smem + SM_V);
    float* score = reinterpret_cast<float*>(smem + SM_SCORE);
    dec_s[tid]        = g_dec_att[b * ATT + tid];
    dec_s[tid + 256]  = g_dec_att[b * ATT + tid + 256];
    v_s[tid]          = __ldg(v_a + tid);
    v_s[tid + 256]    = __ldg(v_a + tid + 256);
    if (tid < MT) score[tid] = 0.f;

    // ldmatrix row base for A
    const int arow = mbase + t8 * 8 + l7;       // A tile: 64 rows
    const int axor = arow & 7;

    // per-thread B base pointer: thread holds W[nbase + g + ...][2c + ...]
    const __half* wbase = g_W_h + (size_t)(nbase + g) * HID + 2 * c;

    // ---- prologue: convert the whole A slab to fp16 smem (only barrier) ----
#pragma unroll
    for (int j = 0; j < 16; ++j) {
        const int q = tid + j * NTHR;
        const int row = q >> 6, k8 = q & 63;          // k8: 16B chunk within row (8 fp16)
        const float4* src = reinterpret_cast<const float4*>(
            enc + ((size_t)(s0 + row) * BATCH + b) * HID) + k8 * 2;
        const float4 v0 = __ldg(src);
        const float4 v1 = __ldg(src + 1);
        uint4 h;
        h.x = cvt2h(v0.x, v0.y);
        h.y = cvt2h(v0.z, v0.w);
        h.z = cvt2h(v1.x, v1.y);
        h.w = cvt2h(v1.z, v1.w);
        const int kc = k8 >> 3, k16 = k8 & 7;
        const uint32_t off = (uint32_t)(kc * 8192 + row * 128 + ((k16 ^ (row & 7)) << 4));
        *reinterpret_cast<uint4*>(smem + OFF_A + off) = h;
    }
    __syncthreads();

    for (int ac = 0; ac < 4; ++ac) {
        const __half* pac = wbase + (size_t)ac * AC_N * HID;

        float acc[2][4][4];
#pragma unroll
        for (int mi = 0; mi < 2; ++mi)
#pragma unroll
            for (int nj = 0; nj < 4; ++nj)
#pragma unroll
                for (int e = 0; e < 4; ++e) acc[mi][nj][e] = 0.f;

        for (int kc = 0; kc < 8; ++kc) {
            const uint32_t uA = sb + OFF_A + kc * 8192;
            const __half* pk = pac + kc * KC;

            uint32_t bf[2][4][2];
            // prefetch ks=0 B fragments
#pragma unroll
            for (int nj = 0; nj < 4; ++nj) {
                bf[0][nj][0] = __ldg(reinterpret_cast<const uint32_t*>(pk + nj * 8 * HID));
                bf[0][nj][1] = __ldg(reinterpret_cast<const uint32_t*>(pk + nj * 8 * HID + 8));
            }
#pragma unroll
            for (int ks = 0; ks < 4; ++ks) {
                if (ks < 3) {
                    const __half* pn = pk + (ks + 1) * 16;
#pragma unroll
                    for (int nj = 0; nj < 4; ++nj) {
                        bf[(ks + 1) & 1][nj][0] =
                            __ldg(reinterpret_cast<const uint32_t*>(pn + nj * 8 * HID));
                        bf[(ks + 1) & 1][nj][1] =
                            __ldg(reinterpret_cast<const uint32_t*>(pn + nj * 8 * HID + 8));
                    }
                }
                const int cb = ks & 1;
                const int acnk = 2 * ks + t16;
                uint32_t a0r[4], a1r[4];
                ldsm4(uA + arow * 128 + ((acnk ^ axor) << 4), a0r);
                ldsm4(uA + (arow + 16) * 128 + ((acnk ^ axor) << 4), a1r);

                MMA(acc[0][0], a0r, bf[cb][0][0], bf[cb][0][1]);
                MMA(acc[0][1], a0r, bf[cb][1][0], bf[cb][1][1]);
                MMA(acc[0][2], a0r, bf[cb][2][0], bf[cb][2][1]);
                MMA(acc[0][3], a0r, bf[cb][3][0], bf[cb][3][1]);
                MMA(acc[1][0], a1r, bf[cb][0][0], bf[cb][0][1]);
                MMA(acc[1][1], a1r, bf[cb][1][0], bf[cb][1][1]);
                MMA(acc[1][2], a1r, bf[cb][2][0], bf[cb][2][1]);
                MMA(acc[1][3], a1r, bf[cb][3][0], bf[cb][3][1]);
            }
        }

        // epilogue for this a-chunk: tanh + v reduction into smem score (atomic, no barrier)
        {
            const int a0 = ac * AC_N;
            float pm[4] = {0.f, 0.f, 0.f, 0.f};
#pragma unroll
            for (int mi = 0; mi < 2; ++mi)
#pragma unroll
                for (int nj = 0; nj < 4; ++nj) {
                    const int n = a0 + nbase + nj * 8 + 2 * c;
                    const float dn0 = dec_s[n], dn1 = dec_s[n + 1];
                    const float vn0 = v_s[n],  vn1 = v_s[n + 1];
                    pm[mi * 2 + 0] += vn0 * tanh_fast(acc[mi][nj][0] + dn0)
                                    + vn1 * tanh_fast(acc[mi][nj][1] + dn1);
                    pm[mi * 2 + 1] += vn0 * tanh_fast(acc[mi][nj][2] + dn0)
                                    + vn1 * tanh_fast(acc[mi][nj][3] + dn1);
                }
            atomicAdd(&score[mbase +  0 + g], pm[0]);
            atomicAdd(&score[mbase +  8 + g], pm[1]);
            atomicAdd(&score[mbase + 16 + g], pm[2]);
            atomicAdd(&score[mbase + 24 + g], pm[3]);
        }
    }

    __syncthreads();
    if (tid < MT) out[(size_t)b * S_LEN + s0 + tid] = score[tid];
}

// ---------------- launch ----------------
extern "C" void kernel_launch(void* const* d_in, const int* in_sizes, int n_in,
                              void* d_out, int out_size) {
    const float* dec_out = (const float*)d_in[0];
    const float* enc     = (const float*)d_in[1];
    const float* W_s     = (const float*)d_in[2];
    const float* W_t     = (const float*)d_in[3];
    const float* b_t     = (const float*)d_in[4];
    const float* v_a     = (const float*)d_in[5];
    float* out = (float*)d_out;
    (void)in_sizes; (void)n_in; (void)out_size;

    cudaFuncSetAttribute(score_mma_kernel,
                         cudaFuncAttributeMaxDynamicSharedMemorySize, SM_TOTAL);

    prep_kernel<<<768, 512>>>(W_s, dec_out, W_t, b_t);

    dim3 grid(S_LEN / MT, BATCH);   // (32, 64) = 2048 CTAs
    score_mma_kernel<<<grid, NTHR, SM_TOTAL>>>(enc, v_a, out);
}

// round 17
// speedup vs baseline: 1.9596x; 1.9596x over previous
#include <cuda_runtime.h>
#include <cuda_fp16.h>
#include <cstdint>

// BahdanauScorer: scores[b,s] = sum_a v_a[a] * tanh( enc[s,b,:].W_s[a,:] + dec[b,:].W_t[a,:] + b_t[a] )
// enc (2048,64,512) f32; dec (64,512); W_s,W_t (512,512); b_t,v_a (512); out (64,2048) f32.
//
// fp16 mma.sync (256 thr, 2x4 warp grid, 32x32 warp tiles, 2 CTAs/SM).
// A slab persistent in smem (conversion streamed into iters 0..6); B double-buffered
// via cp.async; ks-level FRAGMENT double-buffering to hide ldsm->mma latency.

#define S_LEN  2048
#define BATCH  64
#define HID    512
#define ATT    512
#define MT     64       // s-rows per CTA
#define AC_N   128      // a per chunk
#define KC     64       // k per chunk (floats)
#define NTHR   256

// device scratch
__device__ float  g_dec_att[BATCH * ATT];
__device__ __half g_W_h[ATT * HID];

// smem: A 64KB (8 tiles x 8KB, one per kc) + B 2 x 16KB + dec/v/score
#define OFF_A    0
#define OFF_B    65536
#define B_TILE   16384
#define SM_DEC   98304
#define SM_V     100352
#define SM_SCORE 102400
#define SM_TOTAL 102656

__device__ __forceinline__ uint32_t smem_u32(const void* p) {
    uint32_t a;
    asm("{ .reg .u64 t; cvta.to.shared.u64 t, %1; cvt.u32.u64 %0, t; }" : "=r"(a) : "l"(p));
    return a;
}
__device__ __forceinline__ void ldsm4(uint32_t addr, uint32_t* r) {
    asm volatile("ldmatrix.sync.aligned.m8n8.x4.shared.b16 {%0,%1,%2,%3}, [%4];"
                 : "=r"(r[0]), "=r"(r[1]), "=r"(r[2]), "=r"(r[3]) : "r"(addr));
}
__device__ __forceinline__ void cpasync16(uint32_t saddr, const void* gptr) {
    asm volatile("cp.async.cg.shared.global [%0], [%1], 16;" :: "r"(saddr), "l"(gptr) : "memory");
}
#define CP_COMMIT() asm volatile("cp.async.commit_group;" ::: "memory")
#define CP_WAIT0()  asm volatile("cp.async.wait_group 0;" ::: "memory")

#define MMA(d, a, b0, b1)                                                        \
    asm volatile("mma.sync.aligned.m16n8k16.row.col.f32.f16.f16.f32 "            \
                 "{%0,%1,%2,%3},{%4,%5,%6,%7},{%8,%9},{%0,%1,%2,%3};"            \
                 : "+f"((d)[0]), "+f"((d)[1]), "+f"((d)[2]), "+f"((d)[3])        \
                 : "r"((a)[0]), "r"((a)[1]), "r"((a)[2]), "r"((a)[3]),           \
                   "r"(b0), "r"(b1))

__device__ __forceinline__ float tanh_fast(float x) {
    float y;
    asm("tanh.approx.f32 %0, %1;" : "=f"(y) : "f"(x));
    return y;
}
__device__ __forceinline__ uint32_t cvt2h(float x0, float x1) {
    __half2 h = __floats2half2_rn(x0, x1);
    return *reinterpret_cast<uint32_t*>(&h);
}

// ---------------- merged prep kernel ----------------
// blocks 0..511: W_s -> fp16.  blocks 512..767: dec_att (4 blocks per batch).
__global__ void prep_kernel(const float* __restrict__ W_s,
                            const float* __restrict__ dec_out,
                            const float* __restrict__ W_t,
                            const float* __restrict__ b_t) {
    if (blockIdx.x < 512) {
        int i = blockIdx.x * 512 + threadIdx.x;
        g_W_h[i] = __float2half_rn(W_s[i]);
    } else {
        const int bq = blockIdx.x - 512;
        const int b = bq >> 2, aq = bq & 3;
        __shared__ float dsh[HID];
        for (int i = threadIdx.x; i < HID; i += blockDim.x)
            dsh[i] = dec_out[b * HID + i];
        __syncthreads();
        const int a = aq * 128 + (threadIdx.x >> 2);
        const int part = threadIdx.x & 3;
        const float4* w4 = reinterpret_cast<const float4*>(W_t + (size_t)a * HID) + part * 32;
        const float4* d4 = reinterpret_cast<const float4*>(dsh) + part * 32;
        float acc = 0.f;
#pragma unroll 8
        for (int h4 = 0; h4 < 32; ++h4) {
            float4 w = __ldg(&w4[h4]);
            float4 d = d4[h4];
            acc += w.x * d.x + w.y * d.y + w.z * d.z + w.w * d.w;
        }
        acc += __shfl_down_sync(0xffffffffu, acc, 1);
        acc += __shfl_down_sync(0xffffffffu, acc, 2);
        if (part == 0) g_dec_att[b * ATT + a] = acc + b_t[a];
    }
}

// ---------------- main kernel ----------------
extern "C" __global__ void __launch_bounds__(NTHR, 2)
score_mma_kernel(const float* __restrict__ enc,
                 const float* __restrict__ v_a,
                 float* __restrict__ out) {
    extern __shared__ char smem[];
    const uint32_t sb = smem_u32(smem);
    const int tid = threadIdx.x;
    const int lane = tid & 31, wid = tid >> 5;
    const int g = lane >> 2, c = lane & 3, l7 = lane & 7;
    const int t8 = (lane >> 3) & 1, t16 = lane >> 4;
    const int wm = wid & 1, wn = wid >> 1;     // 2 x 4 warp grid
    const int mbase = wm * 32, nbase = wn * 32;
    const int b = blockIdx.y, s0 = blockIdx.x * MT;

    float* dec_s = reinterpret_cast<float*>(smem + SM_DEC);
    float* v_s   = reinterpret_cast<float*>(smem + SM_V);
    float* score = reinterpret_cast<float*>(smem + SM_SCORE);
    dec_s[tid]        = g_dec_att[b * ATT + tid];
    dec_s[tid + 256]  = g_dec_att[b * ATT + tid + 256];
    v_s[tid]          = __ldg(v_a + tid);
    v_s[tid + 256]    = __ldg(v_a + tid + 256);
    if (tid < MT) score[tid] = 0.f;

    // ldmatrix row bases
    const int arow = mbase + t8 * 8 + l7;       // A tile: 64 rows
    const int brow = nbase + t16 * 8 + l7;      // B tile: 128 rows
    const int axor = arow & 7;
    const int bxor = brow & 7;

    // A-tile conversion coords: per tile 512 16B-chunks, 2 per thread.
    const int aq0 = tid * 2, aq1 = tid * 2 + 1;
    const int arow0 = aq0 >> 3, ak0 = aq0 & 7;
    const int arow1 = aq1 >> 3, ak1 = aq1 & 7;
    const uint32_t asw0 = (uint32_t)(arow0 * 128 + ((ak0 ^ (arow0 & 7)) << 4));
    const uint32_t asw1 = (uint32_t)(arow1 * 128 + ((ak1 ^ (arow1 & 7)) << 4));
    const float4* aer0 = reinterpret_cast<const float4*>(
        enc + ((size_t)(s0 + arow0) * BATCH + b) * HID) + ak0 * 2;
    const float4* aer1 = reinterpret_cast<const float4*>(
        enc + ((size_t)(s0 + arow1) * BATCH + b) * HID) + ak1 * 2;

    auto cvt_A_tile = [&](int t) {
        const int kf4 = t * (KC / 4);
        const float4 v0 = __ldg(aer0 + kf4);
        const float4 v1 = __ldg(aer0 + kf4 + 1);
        const float4 v2 = __ldg(aer1 + kf4);
        const float4 v3 = __ldg(aer1 + kf4 + 1);
        uint4 h;
        h.x = cvt2h(v0.x, v0.y); h.y = cvt2h(v0.z, v0.w);
        h.z = cvt2h(v1.x, v1.y); h.w = cvt2h(v1.z, v1.w);
        *reinterpret_cast<uint4*>(smem + OFF_A + t * 8192 + asw0) = h;
        h.x = cvt2h(v2.x, v2.y); h.y = cvt2h(v2.z, v2.w);
        h.z = cvt2h(v3.x, v3.y); h.w = cvt2h(v3.z, v3.w);
        *reinterpret_cast<uint4*>(smem + OFF_A + t * 8192 + asw1) = h;
    };

    // B fill coords: 1024 16B-chunks, 4 per thread
    int brr[4], bkk[4];
    uint32_t swB[4];
#pragma unroll
    for (int j = 0; j < 4; ++j) {
        const int q = tid + j * NTHR;
        brr[j] = q >> 3; bkk[j] = q & 7;
        swB[j] = (uint32_t)(brr[j] * 128 + ((bkk[j] ^ (brr[j] & 7)) << 4));
    }

    auto cp_B = [&](int chunk, int buf) {
        const int a0 = (chunk >> 3) * AC_N, k0 = (chunk & 7) * KC;
        const uint32_t bb = sb + OFF_B + buf * B_TILE;
#pragma unroll
        for (int j = 0; j < 4; ++j) {
            const size_t gg = (size_t)(a0 + brr[j]) * HID + k0 + bkk[j] * 8;
            cpasync16(bb + swB[j], g_W_h + gg);
        }
        CP_COMMIT();
    };

    // ---- prologue: B chunk 0 + A tile 0 (tiles 1..7 streamed into iterations) ----
    cp_B(0, 0);
    cvt_A_tile(0);
    CP_WAIT0();
    __syncthreads();

    float acc[2][4][4];
#pragma unroll
    for (int mi = 0; mi < 2; ++mi)
#pragma unroll
        for (int nj = 0; nj < 4; ++nj)
#pragma unroll
            for (int e = 0; e < 4; ++e) acc[mi][nj][e] = 0.f;

    for (int it = 0; it < 32; ++it) {
        const int cur = it & 1;

        if (it < 31) cp_B(it + 1, 1 ^ cur);
        if (it < 7)  cvt_A_tile(it + 1);

        // ---- mma phase: fragment-double-buffered across ks ----
        const uint32_t uA = sb + OFF_A + (it & 7) * 8192;
        const uint32_t uB = sb + OFF_B + cur * B_TILE;

        uint32_t af[2][8], bfr[2][8];
        {   // load ks=0 fragments
            const int acnk = t16, bcnk = t8;
            ldsm4(uB + brow * 128 + ((bcnk ^ bxor) << 4), &bfr[0][0]);
            ldsm4(uB + (brow + 16) * 128 + ((bcnk ^ bxor) << 4), &bfr[0][4]);
            ldsm4(uA + arow * 128 + ((acnk ^ axor) << 4), &af[0][0]);
            ldsm4(uA + (arow + 16) * 128 + ((acnk ^ axor) << 4), &af[0][4]);
        }
#pragma unroll
        for (int ks = 0; ks < 4; ++ks) {
            if (ks < 3) {   // prefetch ks+1 fragments into the other buffer
                const int nb = (ks + 1) & 1;
                const int acnk = 2 * (ks + 1) + t16;
                const int bcnk = 2 * (ks + 1) + t8;
                ldsm4(uB + brow * 128 + ((bcnk ^ bxor) << 4), &bfr[nb][0]);
                ldsm4(uB + (brow + 16) * 128 + ((bcnk ^ bxor) << 4), &bfr[nb][4]);
                ldsm4(uA + arow * 128 + ((acnk ^ axor) << 4), &af[nb][0]);
                ldsm4(uA + (arow + 16) * 128 + ((acnk ^ axor) << 4), &af[nb][4]);
            }
            const int cb = ks & 1;
            MMA(acc[0][0], &af[cb][0], bfr[cb][0], bfr[cb][1]);
            MMA(acc[0][1], &af[cb][0], bfr[cb][2], bfr[cb][3]);
            MMA(acc[0][2], &af[cb][0], bfr[cb][4], bfr[cb][5]);
            MMA(acc[0][3], &af[cb][0], bfr[cb][6], bfr[cb][7]);
            MMA(acc[1][0], &af[cb][4], bfr[cb][0], bfr[cb][1]);
            MMA(acc[1][1], &af[cb][4], bfr[cb][2], bfr[cb][3]);
            MMA(acc[1][2], &af[cb][4], bfr[cb][4], bfr[cb][5]);
            MMA(acc[1][3], &af[cb][4], bfr[cb][6], bfr[cb][7]);
        }

        // end of an a-chunk: tanh + v reduction, reset accumulators
        if ((it & 7) == 7) {
            const int a0 = (it >> 3) * AC_N;
            float pm[4] = {0.f, 0.f, 0.f, 0.f};
#pragma unroll
            for (int mi = 0; mi < 2; ++mi)
#pragma unroll
                for (int nj = 0; nj < 4; ++nj) {
                    const int n = a0 + nbase + nj * 8 + 2 * c;
                    const float dn0 = dec_s[n], dn1 = dec_s[n + 1];
                    const float vn0 = v_s[n],  vn1 = v_s[n + 1];
                    pm[mi * 2 + 0] += vn0 * tanh_fast(acc[mi][nj][0] + dn0)
                                    + vn1 * tanh_fast(acc[mi][nj][1] + dn1);
                    pm[mi * 2 + 1] += vn0 * tanh_fast(acc[mi][nj][2] + dn0)
                                    + vn1 * tanh_fast(acc[mi][nj][3] + dn1);
                }
            atomicAdd(&score[mbase +  0 + g], pm[0]);
            atomicAdd(&score[mbase +  8 + g], pm[1]);
            atomicAdd(&score[mbase + 16 + g], pm[2]);
            atomicAdd(&score[mbase + 24 + g], pm[3]);
#pragma unroll
            for (int mi = 0; mi < 2; ++mi)
#pragma unroll
                for (int nj = 0; nj < 4; ++nj)
#pragma unroll
                    for (int e = 0; e < 4; ++e) acc[mi][nj][e] = 0.f;
        }

        if (it < 31) CP_WAIT0();
        __syncthreads();
    }

    if (tid < MT) out[(size_t)b * S_LEN + s0 + tid] = score[tid];
}

// ---------------- launch ----------------
extern "C" void kernel_launch(void* const* d_in, const int* in_sizes, int n_in,
                              void* d_out, int out_size) {
    const float* dec_out = (const float*)d_in[0];
    const float* enc     = (const float*)d_in[1];
    const float* W_s     = (const float*)d_in[2];
    const float* W_t     = (const float*)d_in[3];
    const float* b_t     = (const float*)d_in[4];
    const float* v_a     = (const float*)d_in[5];
    float* out = (float*)d_out;
    (void)in_sizes; (void)n_in; (void)out_size;

    cudaFuncSetAttribute(score_mma_kernel,
                         cudaFuncAttributeMaxDynamicSharedMemorySize, SM_TOTAL);

    prep_kernel<<<768, 512>>>(W_s, dec_out, W_t, b_t);

    dim3 grid(S_LEN / MT, BATCH);   // (32, 64) = 2048 CTAs
    score_mma_kernel<<<grid, NTHR, SM_TOTAL>>>(enc, v_a, out);
}